// round 10
// baseline (speedup 1.0000x reference)
#include <cuda_runtime.h>
#include <cuda_bf16.h>
#include <cstdint>

// Problem: B=8, S=2048, N=4, D=1024
//   mixed[b,s,i,d] = sum_j h_res[b,s,i,j] * x[b,s,j,d]
//   out = mixed * h_out[b,s,d] + h_post[b,s,i] * x[b,s,i,d]
//
// TWO tokens per CTA, 256 threads, all 10 big 128-bit loads front-batched
// (MLP_p1 = 10). __launch_bounds__(256, 4) caps registers at 64 so 4 CTAs
// co-reside per SM (32 warps, 50% occ) -> ~320 outstanding loads/SM.

#define TOKENS (8 * 2048)
#define D_DIM 1024
#define D4 (D_DIM / 4)   // 256

__global__ __launch_bounds__(256, 4)
void stream_mix_kernel2(const float* __restrict__ x,
                        const float* __restrict__ h_res,
                        const float* __restrict__ h_out,
                        const float* __restrict__ h_post,
                        float* __restrict__ out) {
    const int tok0 = blockIdx.x * 2;     // even token
    const int d4   = threadIdx.x;        // 0 .. 255

    __shared__ float4 s_hr[2][4];        // h_res rows for both tokens
    __shared__ float4 s_hp[2];           // h_post for both tokens

    const int tid = threadIdx.x;
    if (tid < 8) {
        const int t = tid >> 2;          // which token
        const int r = tid & 3;           // which row
        s_hr[t][r] = reinterpret_cast<const float4*>(
            h_res + (size_t)(tok0 + t) * 16)[r];
    } else if (tid < 10) {
        const int t = tid - 8;
        s_hp[t] = reinterpret_cast<const float4*>(
            h_post + (size_t)(tok0 + t) * 4)[0];
    }

    // Front-batch ALL big loads for both tokens (10 independent LDG.128).
    const float4* xa =
        reinterpret_cast<const float4*>(x + (size_t)tok0 * 4 * D_DIM);
    const float4* xb = xa + 4 * D4;      // next token's x block

    const float4 a0 = __ldcs(&xa[0 * D4 + d4]);
    const float4 a1 = __ldcs(&xa[1 * D4 + d4]);
    const float4 a2 = __ldcs(&xa[2 * D4 + d4]);
    const float4 a3 = __ldcs(&xa[3 * D4 + d4]);
    const float4 b0 = __ldcs(&xb[0 * D4 + d4]);
    const float4 b1 = __ldcs(&xb[1 * D4 + d4]);
    const float4 b2 = __ldcs(&xb[2 * D4 + d4]);
    const float4 b3 = __ldcs(&xb[3 * D4 + d4]);
    const float4 hoa = __ldcs(
        &reinterpret_cast<const float4*>(h_out + (size_t)tok0 * D_DIM)[d4]);
    const float4 hob = __ldcs(
        &reinterpret_cast<const float4*>(h_out + (size_t)(tok0 + 1) * D_DIM)[d4]);

    __syncthreads();

    float4* oa = reinterpret_cast<float4*>(out + (size_t)tok0 * 4 * D_DIM);
    float4* ob = oa + 4 * D4;

    // ---- Token A ----
    {
        const float4 hp = s_hp[0];
        {
            const float4 hr = s_hr[0][0];
            float4 o;
            o.x = (hr.x*a0.x + hr.y*a1.x + hr.z*a2.x + hr.w*a3.x) * hoa.x + hp.x*a0.x;
            o.y = (hr.x*a0.y + hr.y*a1.y + hr.z*a2.y + hr.w*a3.y) * hoa.y + hp.x*a0.y;
            o.z = (hr.x*a0.z + hr.y*a1.z + hr.z*a2.z + hr.w*a3.z) * hoa.z + hp.x*a0.z;
            o.w = (hr.x*a0.w + hr.y*a1.w + hr.z*a2.w + hr.w*a3.w) * hoa.w + hp.x*a0.w;
            __stcs(&oa[0 * D4 + d4], o);
        }
        {
            const float4 hr = s_hr[0][1];
            float4 o;
            o.x = (hr.x*a0.x + hr.y*a1.x + hr.z*a2.x + hr.w*a3.x) * hoa.x + hp.y*a1.x;
            o.y = (hr.x*a0.y + hr.y*a1.y + hr.z*a2.y + hr.w*a3.y) * hoa.y + hp.y*a1.y;
            o.z = (hr.x*a0.z + hr.y*a1.z + hr.z*a2.z + hr.w*a3.z) * hoa.z + hp.y*a1.z;
            o.w = (hr.x*a0.w + hr.y*a1.w + hr.z*a2.w + hr.w*a3.w) * hoa.w + hp.y*a1.w;
            __stcs(&oa[1 * D4 + d4], o);
        }
        {
            const float4 hr = s_hr[0][2];
            float4 o;
            o.x = (hr.x*a0.x + hr.y*a1.x + hr.z*a2.x + hr.w*a3.x) * hoa.x + hp.z*a2.x;
            o.y = (hr.x*a0.y + hr.y*a1.y + hr.z*a2.y + hr.w*a3.y) * hoa.y + hp.z*a2.y;
            o.z = (hr.x*a0.z + hr.y*a1.z + hr.z*a2.z + hr.w*a3.z) * hoa.z + hp.z*a2.z;
            o.w = (hr.x*a0.w + hr.y*a1.w + hr.z*a2.w + hr.w*a3.w) * hoa.w + hp.z*a2.w;
            __stcs(&oa[2 * D4 + d4], o);
        }
        {
            const float4 hr = s_hr[0][3];
            float4 o;
            o.x = (hr.x*a0.x + hr.y*a1.x + hr.z*a2.x + hr.w*a3.x) * hoa.x + hp.w*a3.x;
            o.y = (hr.x*a0.y + hr.y*a1.y + hr.z*a2.y + hr.w*a3.y) * hoa.y + hp.w*a3.y;
            o.z = (hr.x*a0.z + hr.y*a1.z + hr.z*a2.z + hr.w*a3.z) * hoa.z + hp.w*a3.z;
            o.w = (hr.x*a0.w + hr.y*a1.w + hr.z*a2.w + hr.w*a3.w) * hoa.w + hp.w*a3.w;
            __stcs(&oa[3 * D4 + d4], o);
        }
    }

    // ---- Token B ----
    {
        const float4 hp = s_hp[1];
        {
            const float4 hr = s_hr[1][0];
            float4 o;
            o.x = (hr.x*b0.x + hr.y*b1.x + hr.z*b2.x + hr.w*b3.x) * hob.x + hp.x*b0.x;
            o.y = (hr.x*b0.y + hr.y*b1.y + hr.z*b2.y + hr.w*b3.y) * hob.y + hp.x*b0.y;
            o.z = (hr.x*b0.z + hr.y*b1.z + hr.z*b2.z + hr.w*b3.z) * hob.z + hp.x*b0.z;
            o.w = (hr.x*b0.w + hr.y*b1.w + hr.z*b2.w + hr.w*b3.w) * hob.w + hp.x*b0.w;
            __stcs(&ob[0 * D4 + d4], o);
        }
        {
            const float4 hr = s_hr[1][1];
            float4 o;
            o.x = (hr.x*b0.x + hr.y*b1.x + hr.z*b2.x + hr.w*b3.x) * hob.x + hp.y*b1.x;
            o.y = (hr.x*b0.y + hr.y*b1.y + hr.z*b2.y + hr.w*b3.y) * hob.y + hp.y*b1.y;
            o.z = (hr.x*b0.z + hr.y*b1.z + hr.z*b2.z + hr.w*b3.z) * hob.z + hp.y*b1.z;
            o.w = (hr.x*b0.w + hr.y*b1.w + hr.z*b2.w + hr.w*b3.w) * hob.w + hp.y*b1.w;
            __stcs(&ob[1 * D4 + d4], o);
        }
        {
            const float4 hr = s_hr[1][2];
            float4 o;
            o.x = (hr.x*b0.x + hr.y*b1.x + hr.z*b2.x + hr.w*b3.x) * hob.x + hp.z*b2.x;
            o.y = (hr.x*b0.y + hr.y*b1.y + hr.z*b2.y + hr.w*b3.y) * hob.y + hp.z*b2.y;
            o.z = (hr.x*b0.z + hr.y*b1.z + hr.z*b2.z + hr.w*b3.z) * hob.z + hp.z*b2.z;
            o.w = (hr.x*b0.w + hr.y*b1.w + hr.z*b2.w + hr.w*b3.w) * hob.w + hp.z*b2.w;
            __stcs(&ob[2 * D4 + d4], o);
        }
        {
            const float4 hr = s_hr[1][3];
            float4 o;
            o.x = (hr.x*b0.x + hr.y*b1.x + hr.z*b2.x + hr.w*b3.x) * hob.x + hp.w*b3.x;
            o.y = (hr.x*b0.y + hr.y*b1.y + hr.z*b2.y + hr.w*b3.y) * hob.y + hp.w*b3.y;
            o.z = (hr.x*b0.z + hr.y*b1.z + hr.z*b2.z + hr.w*b3.z) * hob.z + hp.w*b3.z;
            o.w = (hr.x*b0.w + hr.y*b1.w + hr.z*b2.w + hr.w*b3.w) * hob.w + hp.w*b3.w;
            __stcs(&ob[3 * D4 + d4], o);
        }
    }
}

extern "C" void kernel_launch(void* const* d_in, const int* in_sizes, int n_in,
                              void* d_out, int out_size) {
    const float* x      = (const float*)d_in[0];  // [8,2048,4,1024]
    const float* h_res  = (const float*)d_in[1];  // [8,2048,4,4]
    const float* h_out  = (const float*)d_in[2];  // [8,2048,1024]
    const float* h_post = (const float*)d_in[3];  // [8,2048,4]
    float* out = (float*)d_out;                   // [8,2048,4,1024]

    stream_mix_kernel2<<<TOKENS / 2, 256>>>(x, h_res, h_out, h_post, out);
}